// round 6
// baseline (speedup 1.0000x reference)
#include <cuda_runtime.h>
#include <cuda_bf16.h>
#include <cstdint>

// Segment-sum of weighted RGB over sorted ray indices.
// pred_rgb[r, c] = sum_{i : ray_indices[i]==r} weights[i] * rgb[i, c]
//
// Persistent kernel, cp.async double-buffered tile pipeline:
//  - 2 blocks/SM x 512 threads, tiles of 2048 samples (40KB/stage, 2 stages).
//  - cp.async.cg streams rgb/w/idx gmem->smem for tile i+1 while tile i computes.
//  - compute: each thread owns 4 consecutive samples; run-length accumulate
//    over sorted indices, flush via atomicAdd (RED) on boundary.
//  - rgb smem reads: 3x LDS.128 at word-stride 12/lane -> conflict-free phases.

#define BLOCK 512
#define IPT 4
#define TILE (BLOCK * IPT)                 // 2048 samples / tile
#define STAGE_F4 2560                      // float4 per stage: rgb 1536 + w 512 + idx 512
#define STAGE_BYTES (STAGE_F4 * 16)        // 40960
#define SMEM_BYTES (2 * STAGE_BYTES)       // 81920
#define GRID 296                           // 2 blocks per SM (148 SMs)

__global__ void zero_out_kernel4(float4* __restrict__ out, int n4) {
    int i = blockIdx.x * blockDim.x + threadIdx.x;
    if (i < n4) out[i] = make_float4(0.f, 0.f, 0.f, 0.f);
}
__global__ void zero_out_tail(float* __restrict__ out, int start, int n) {
    int i = start + blockIdx.x * blockDim.x + threadIdx.x;
    if (i < n) out[i] = 0.0f;
}

__device__ __forceinline__ void cp_async16(uint32_t saddr, const void* gptr) {
    asm volatile("cp.async.cg.shared.global [%0], [%1], 16;" :: "r"(saddr), "l"(gptr));
}
__device__ __forceinline__ void cp_commit() {
    asm volatile("cp.async.commit_group;");
}
template <int N>
__device__ __forceinline__ void cp_wait() {
    asm volatile("cp.async.wait_group %0;" :: "n"(N));
}
__device__ __forceinline__ uint32_t smem_u32(const void* p) {
    return (uint32_t)__cvta_generic_to_shared(p);
}

__global__ __launch_bounds__(BLOCK, 2) void integrate_kernel(
    const float* __restrict__ rgbf,   // [N*3]
    const float* __restrict__ wf,     // [N]
    const int*   __restrict__ idxf,   // [N]
    float* __restrict__ out,
    int n_samples)
{
    extern __shared__ float4 smem[];  // 2 stages x STAGE_F4 float4
    const int tid = threadIdx.x;
    const uint32_t sbase = smem_u32(smem);

    const int n_tiles = n_samples / TILE;      // full tiles
    // my tiles: blockIdx.x, blockIdx.x + GRID, ...
    int my_n = 0;
    for (int t = blockIdx.x; t < n_tiles; t += gridDim.x) my_n++;

    auto prefetch = [&](int tile, int stage) {
        const float4* rgb4 = (const float4*)rgbf + (size_t)tile * (TILE * 3 / 4);
        const float4* w4   = (const float4*)wf   + (size_t)tile * (TILE / 4);
        const int4*   i4   = (const int4*)idxf   + (size_t)tile * (TILE / 4);
        uint32_t sb = sbase + stage * STAGE_BYTES;
#pragma unroll
        for (int s = 0; s < 3; s++)
            cp_async16(sb + (uint32_t)(s * BLOCK + tid) * 16, rgb4 + s * BLOCK + tid);
        cp_async16(sb + (uint32_t)(1536 + tid) * 16, w4 + tid);
        cp_async16(sb + (uint32_t)(2048 + tid) * 16, i4 + tid);
        cp_commit();
    };

    if (my_n > 0) {
        prefetch(blockIdx.x, 0);

        for (int i = 0; i < my_n; i++) {
            if (i + 1 < my_n) {
                prefetch(blockIdx.x + (i + 1) * gridDim.x, (i + 1) & 1);
                cp_wait<1>();
            } else {
                cp_wait<0>();
            }
            __syncthreads();

            const float4* st = smem + (size_t)(i & 1) * STAGE_F4;
            // rgb: 3x LDS.128, word stride 12 per lane -> conflict-free
            float4 r0 = st[3 * tid + 0];
            float4 r1 = st[3 * tid + 1];
            float4 r2 = st[3 * tid + 2];
            float4 wv = st[1536 + tid];
            int4   iv = *reinterpret_cast<const int4*>(&st[2048 + tid]);

            float rf[12] = {r0.x, r0.y, r0.z, r0.w,
                            r1.x, r1.y, r1.z, r1.w,
                            r2.x, r2.y, r2.z, r2.w};
            float w[4]  = {wv.x, wv.y, wv.z, wv.w};
            int  idx[4] = {iv.x, iv.y, iv.z, iv.w};

            int cur = idx[0];
            float a0 = 0.f, a1 = 0.f, a2 = 0.f;
#pragma unroll
            for (int k = 0; k < IPT; k++) {
                int ik = idx[k];
                if (ik != cur) {
                    atomicAdd(&out[3 * cur + 0], a0);
                    atomicAdd(&out[3 * cur + 1], a1);
                    atomicAdd(&out[3 * cur + 2], a2);
                    cur = ik;
                    a0 = a1 = a2 = 0.f;
                }
                a0 = fmaf(w[k], rf[3 * k + 0], a0);
                a1 = fmaf(w[k], rf[3 * k + 1], a1);
                a2 = fmaf(w[k], rf[3 * k + 2], a2);
            }
            atomicAdd(&out[3 * cur + 0], a0);
            atomicAdd(&out[3 * cur + 1], a1);
            atomicAdd(&out[3 * cur + 2], a2);

            __syncthreads();   // stage may be overwritten by next prefetch
        }
    }

    // tail samples beyond full tiles: per-sample, grid-strided
    long tail_start = (long)n_tiles * TILE;
    for (long s = tail_start + (long)blockIdx.x * BLOCK + tid; s < n_samples;
         s += (long)gridDim.x * BLOCK) {
        int r = idxf[s];
        float ws = wf[s];
        atomicAdd(&out[3 * r + 0], ws * rgbf[3 * s + 0]);
        atomicAdd(&out[3 * r + 1], ws * rgbf[3 * s + 1]);
        atomicAdd(&out[3 * r + 2], ws * rgbf[3 * s + 2]);
    }
}

extern "C" void kernel_launch(void* const* d_in, const int* in_sizes, int n_in,
                              void* d_out, int out_size) {
    const float* rgb = (const float*)d_in[0];
    const float* wts = (const float*)d_in[1];
    const int*   idx = (const int*)d_in[2];
    float* out = (float*)d_out;

    int n_samples = in_sizes[2];

    // zero-init output (poisoned by harness; empty rays must be 0)
    {
        int n4 = out_size / 4;
        int threads = 256;
        int blocks = (n4 + threads - 1) / threads;
        if (blocks > 0)
            zero_out_kernel4<<<blocks, threads>>>((float4*)out, n4);
        if (out_size - n4 * 4 > 0)
            zero_out_tail<<<1, 32>>>(out, n4 * 4, out_size);
    }

    // main segment-sum (persistent, dynamic smem 80KB)
    {
        static bool attr_set = false;
        // setting an attribute is idempotent & deterministic; do it every call
        cudaFuncSetAttribute(integrate_kernel,
                             cudaFuncAttributeMaxDynamicSharedMemorySize,
                             SMEM_BYTES);
        (void)attr_set;
        integrate_kernel<<<GRID, BLOCK, SMEM_BYTES>>>(rgb, wts, idx, out, n_samples);
    }
}

// round 9
// speedup vs baseline: 1.1816x; 1.1816x over previous
#include <cuda_runtime.h>
#include <cuda_bf16.h>

// Segment-sum of weighted RGB over sorted ray indices.
// pred_rgb[r, c] = sum_{i : ray_indices[i]==r} weights[i] * rgb[i, c]
//
// Round-1 structure (best so far, 19.2us) with ALL streaming loads switched
// to ld.global.cv (L1-bypass). Hypothesis: the ~4.3 TB/s plateau across all
// prior variants is the SM-wide outstanding-LDG queue (~64 req x 128B at
// ~600cyc loaded latency); the .cv path is tracked differently and measured
// at ~6300 B/cyc chip throughput.

#define IPT 8  // samples per thread; rgb bytes per thread = 96 (16B-aligned)

__device__ __forceinline__ float4 ldcv_f4(const float4* p) {
    float4 v;
    asm volatile("ld.global.cv.v4.f32 {%0,%1,%2,%3}, [%4];"
                 : "=f"(v.x), "=f"(v.y), "=f"(v.z), "=f"(v.w) : "l"(p));
    return v;
}
__device__ __forceinline__ int4 ldcv_i4(const int4* p) {
    int4 v;
    asm volatile("ld.global.cv.v4.u32 {%0,%1,%2,%3}, [%4];"
                 : "=r"(v.x), "=r"(v.y), "=r"(v.z), "=r"(v.w) : "l"(p));
    return v;
}

__global__ void zero_out_kernel4(float4* __restrict__ out, int n4) {
    int i = blockIdx.x * blockDim.x + threadIdx.x;
    if (i < n4) out[i] = make_float4(0.f, 0.f, 0.f, 0.f);
}
__global__ void zero_out_tail(float* __restrict__ out, int start, int n) {
    int i = start + blockIdx.x * blockDim.x + threadIdx.x;
    if (i < n) out[i] = 0.0f;
}

__global__ __launch_bounds__(256) void integrate_kernel(
    const float4* __restrict__ rgb4,   // 3*N/4 float4
    const float4* __restrict__ w4,     // N/4 float4
    const int4*  __restrict__ idx4,    // N/4 int4
    float* __restrict__ out,
    int n_samples)
{
    int t = blockIdx.x * blockDim.x + threadIdx.x;
    long base = (long)t * IPT;
    if (base >= n_samples) return;

    // ---- 10 independent L1-bypass vector loads per thread ----
    int4   i0 = ldcv_i4(idx4 + t * 2 + 0);
    int4   i1 = ldcv_i4(idx4 + t * 2 + 1);
    float4 w0 = ldcv_f4(w4 + t * 2 + 0);
    float4 w1 = ldcv_f4(w4 + t * 2 + 1);
    float4 r[6];
#pragma unroll
    for (int k = 0; k < 6; k++) r[k] = ldcv_f4(rgb4 + t * 6 + k);

    const float* rf = reinterpret_cast<const float*>(r);
    int   idx[IPT] = {i0.x, i0.y, i0.z, i0.w, i1.x, i1.y, i1.z, i1.w};
    float w[IPT]   = {w0.x, w0.y, w0.z, w0.w, w1.x, w1.y, w1.z, w1.w};

    // ---- run-length accumulate over sorted indices, flush on change ----
    int cur = idx[0];
    float a0 = 0.f, a1 = 0.f, a2 = 0.f;
#pragma unroll
    for (int k = 0; k < IPT; k++) {
        int ik = idx[k];
        if (ik != cur) {
            atomicAdd(&out[3 * cur + 0], a0);
            atomicAdd(&out[3 * cur + 1], a1);
            atomicAdd(&out[3 * cur + 2], a2);
            cur = ik;
            a0 = a1 = a2 = 0.f;
        }
        a0 = fmaf(w[k], rf[3 * k + 0], a0);
        a1 = fmaf(w[k], rf[3 * k + 1], a1);
        a2 = fmaf(w[k], rf[3 * k + 2], a2);
    }
    atomicAdd(&out[3 * cur + 0], a0);
    atomicAdd(&out[3 * cur + 1], a1);
    atomicAdd(&out[3 * cur + 2], a2);
}

extern "C" void kernel_launch(void* const* d_in, const int* in_sizes, int n_in,
                              void* d_out, int out_size) {
    const float* rgb = (const float*)d_in[0];
    const float* wts = (const float*)d_in[1];
    const int*   idx = (const int*)d_in[2];
    float* out = (float*)d_out;

    int n_samples = in_sizes[2];

    // zero-init output (poisoned by harness; empty rays must be 0)
    {
        int n4 = out_size / 4;
        int threads = 256;
        int blocks = (n4 + threads - 1) / threads;
        if (blocks > 0)
            zero_out_kernel4<<<blocks, threads>>>((float4*)out, n4);
        if (out_size - n4 * 4 > 0)
            zero_out_tail<<<1, 32>>>(out, n4 * 4, out_size);
    }

    // main segment-sum
    {
        int total_threads = (n_samples + IPT - 1) / IPT;
        int threads = 256;
        int blocks = (total_threads + threads - 1) / threads;
        integrate_kernel<<<blocks, threads>>>(
            (const float4*)rgb, (const float4*)wts, (const int4*)idx,
            out, n_samples);
    }
}